// round 13
// baseline (speedup 1.0000x reference)
#include <cuda_runtime.h>

// ---------------------------------------------------------------------------
// LearnableWaveletTransform, two-phase:
//  Phase 1 coeff_k   : composed direct filters -> compact coefficient arrays
//  Phase 2 assemble2_k: zero-extend + slot assembly, RT=4 s/thread (MLP=4)
//
//   x: [B=8, S=4096, F=128] f32  ->  out: [6, B, 4096, F] f32
//   slots: [lo3, hi1, hi2, hi3, hi1+hi2+hi3, lo3]
//
//   hi1[s] = sum_{j<8}  Khi[j]  * x[2s-6  + j]      (s < 2051)
//   hi2[s] = sum_{j<22} C2hi[j] * x[4s-18 + j]      (s < 1029)
//   lo3[s] = sum_{j<50} C3lo[j] * x[8s-42 + j]      (s < 518)   (hi3 same taps)
// ---------------------------------------------------------------------------

#define NB   8
#define S0   4096
#define S1   2051
#define S2   1029
#define S3   518
#define F4   32                            // 128 floats = 32 float4
#define SLOTSZ ((size_t)NB * S0 * F4)      // float4 elems per output slot
#define RT   4

// Segmented grid for phase 1 (level-3 heavy blocks first)
#define NBLK3 33                            // ceil(518/16)
#define NBLK2 65                            // ceil(1029/16)
#define NBLK1 129                           // ceil(2051/16)

// Compact scratch (~16.8 MB total)
__device__ float4 g_h1[NB * S1 * F4];
__device__ float4 g_h2[NB * S2 * F4];
__device__ float4 g_h3[NB * S3 * F4];
__device__ float4 g_l3[NB * S3 * F4];

struct Filt {
    float Klo[8], Khi[8], C2lo[22], C2hi[22], C3lo[50], C3hi[50];
    constexpr Filt()
        : Klo{ 0.23037781330885523f,  0.7148465705525415f,   0.6308807679295904f,
              -0.02798376941698385f, -0.18703481171888114f,  0.030841381835986965f,
               0.032883011666982945f, -0.010597401784997278f },
          Khi{ -0.010597401784997278f, 0.032883011666982945f, 0.030841381835986965f,
                0.18703481171888114f, -0.02798376941698385f, -0.6308807679295904f,
                0.7148465705525415f,  -0.23037781330885523f },
          C2lo{}, C2hi{}, C3lo{}, C3hi{} {
        for (int j = 0; j < 22; ++j) {
            float alo = 0.f, ahi = 0.f;
            for (int u = 0; u < 8; ++u) {
                const int t = j - 2 * u;
                if (t >= 0 && t < 8) { alo += Klo[u] * Klo[t]; ahi += Khi[u] * Klo[t]; }
            }
            C2lo[j] = alo; C2hi[j] = ahi;
        }
        for (int j = 0; j < 50; ++j) {
            float alo = 0.f, ahi = 0.f;
            for (int v = 0; v < 8; ++v) {
                const int t = j - 4 * v;
                if (t >= 0 && t < 22) { alo += Klo[v] * C2lo[t]; ahi += Khi[v] * C2lo[t]; }
            }
            C3lo[j] = alo; C3hi[j] = ahi;
        }
    }
};
__constant__ Filt FF = Filt();

__device__ __forceinline__ void fma4(float4& a, float c, const float4& v) {
    a.x = fmaf(c, v.x, a.x); a.y = fmaf(c, v.y, a.y);
    a.z = fmaf(c, v.z, a.z); a.w = fmaf(c, v.w, a.w);
}
__device__ __forceinline__ void add4(float4& a, const float4& v) {
    a.x += v.x; a.y += v.y; a.z += v.z; a.w += v.w;
}
__device__ __forceinline__ float4 zero4() { return make_float4(0.f, 0.f, 0.f, 0.f); }

// ------------------------------- Phase 1 -----------------------------------
__global__ __launch_bounds__(128)
void coeff_k(const float4* __restrict__ x) {
    const int f4 = threadIdx.x;                   // 0..31
    const int b  = blockIdx.y;
    const float4* __restrict__ xb = x + (size_t)b * (S0 * F4) + f4;
    const int seg = blockIdx.x;

    if (seg < NBLK3) {
        // ---- level 3: lo3 & hi3, 50 taps, stride 8, span 74 ----
        const int sb = seg * 16 + threadIdx.y * RT;
        float4 al[RT], ah[RT];
#pragma unroll
        for (int r = 0; r < RT; ++r) { al[r] = zero4(); ah[r] = zero4(); }
        const int base = 8 * sb - 42;
        if (base >= 0 && base + 74 <= S0) {       // interior (all s valid)
#pragma unroll
            for (int k = 0; k < 74; ++k) {
                const float4 v = __ldg(xb + (size_t)(base + k) * F4);
#pragma unroll
                for (int r = 0; r < RT; ++r) {
                    const int j = k - 8 * r;
                    if (j >= 0 && j < 50) {
                        fma4(al[r], FF.C3lo[j], v);
                        fma4(ah[r], FF.C3hi[j], v);
                    }
                }
            }
#pragma unroll
            for (int r = 0; r < RT; ++r) {
                const size_t o = ((size_t)(b * S3 + sb + r)) * F4 + f4;
                g_l3[o] = al[r];
                g_h3[o] = ah[r];
            }
        } else if (sb < S3) {                      // boundary
#pragma unroll
            for (int k = 0; k < 74; ++k) {
                const int xs = base + k;
                if (xs >= 0 && xs < S0) {
                    const float4 v = __ldg(xb + (size_t)xs * F4);
#pragma unroll
                    for (int r = 0; r < RT; ++r) {
                        const int j = k - 8 * r;
                        if (j >= 0 && j < 50 && (sb + r) < S3) {
                            fma4(al[r], FF.C3lo[j], v);
                            fma4(ah[r], FF.C3hi[j], v);
                        }
                    }
                }
            }
#pragma unroll
            for (int r = 0; r < RT; ++r) {
                if ((sb + r) < S3) {
                    const size_t o = ((size_t)(b * S3 + sb + r)) * F4 + f4;
                    g_l3[o] = al[r];
                    g_h3[o] = ah[r];
                }
            }
        }
    } else if (seg < NBLK3 + NBLK2) {
        // ---- level 2: hi2, 22 taps, stride 4, span 34 ----
        const int sb = (seg - NBLK3) * 16 + threadIdx.y * RT;
        float4 acc[RT];
#pragma unroll
        for (int r = 0; r < RT; ++r) acc[r] = zero4();
        const int base = 4 * sb - 18;
        if (base >= 0 && base + 34 <= S0) {
#pragma unroll
            for (int k = 0; k < 34; ++k) {
                const float4 v = __ldg(xb + (size_t)(base + k) * F4);
#pragma unroll
                for (int r = 0; r < RT; ++r) {
                    const int j = k - 4 * r;
                    if (j >= 0 && j < 22) fma4(acc[r], FF.C2hi[j], v);
                }
            }
#pragma unroll
            for (int r = 0; r < RT; ++r)
                g_h2[((size_t)(b * S2 + sb + r)) * F4 + f4] = acc[r];
        } else if (sb < S2) {
#pragma unroll
            for (int k = 0; k < 34; ++k) {
                const int xs = base + k;
                if (xs >= 0 && xs < S0) {
                    const float4 v = __ldg(xb + (size_t)xs * F4);
#pragma unroll
                    for (int r = 0; r < RT; ++r) {
                        const int j = k - 4 * r;
                        if (j >= 0 && j < 22 && (sb + r) < S2)
                            fma4(acc[r], FF.C2hi[j], v);
                    }
                }
            }
#pragma unroll
            for (int r = 0; r < RT; ++r)
                if ((sb + r) < S2)
                    g_h2[((size_t)(b * S2 + sb + r)) * F4 + f4] = acc[r];
        }
    } else {
        // ---- level 1: hi1, 8 taps, stride 2, span 14 ----
        const int sb = (seg - NBLK3 - NBLK2) * 16 + threadIdx.y * RT;
        float4 acc[RT];
#pragma unroll
        for (int r = 0; r < RT; ++r) acc[r] = zero4();
        const int base = 2 * sb - 6;
        if (base >= 0 && base + 14 <= S0) {
#pragma unroll
            for (int k = 0; k < 14; ++k) {
                const float4 v = __ldg(xb + (size_t)(base + k) * F4);
#pragma unroll
                for (int r = 0; r < RT; ++r) {
                    const int j = k - 2 * r;
                    if (j >= 0 && j < 8) fma4(acc[r], FF.Khi[j], v);
                }
            }
#pragma unroll
            for (int r = 0; r < RT; ++r)
                g_h1[((size_t)(b * S1 + sb + r)) * F4 + f4] = acc[r];
        } else if (sb < S1) {
#pragma unroll
            for (int k = 0; k < 14; ++k) {
                const int xs = base + k;
                if (xs >= 0 && xs < S0) {
                    const float4 v = __ldg(xb + (size_t)xs * F4);
#pragma unroll
                    for (int r = 0; r < RT; ++r) {
                        const int j = k - 2 * r;
                        if (j >= 0 && j < 8 && (sb + r) < S1)
                            fma4(acc[r], FF.Khi[j], v);
                    }
                }
            }
#pragma unroll
            for (int r = 0; r < RT; ++r)
                if ((sb + r) < S1)
                    g_h1[((size_t)(b * S1 + sb + r)) * F4 + f4] = acc[r];
        }
    }
}

// ------------------------------- Phase 2 -----------------------------------
// 1.57M threads; each handles RT=4 consecutive s for one (slot,b,f4).
// idx bits: [4:0]=f4, [14:5]=s-group (1024), [17:15]=b, [20:18]=slot.
__global__ __launch_bounds__(256)
void assemble2_k(float4* __restrict__ out) {
    const int idx  = blockIdx.x * 256 + threadIdx.x;
    const int f4   = idx & 31;
    const int sg   = (idx >> 5) & 1023;
    const int b    = (idx >> 15) & 7;
    const int slot = idx >> 18;
    const int s0   = sg * RT;

    float4 v[RT];
#pragma unroll
    for (int r = 0; r < RT; ++r) v[r] = zero4();

    if (slot == 1) {
#pragma unroll
        for (int r = 0; r < RT; ++r)
            if (s0 + r < S1) v[r] = __ldg(&g_h1[((size_t)(b * S1 + s0 + r)) * F4 + f4]);
    } else if (slot == 2) {
#pragma unroll
        for (int r = 0; r < RT; ++r)
            if (s0 + r < S2) v[r] = __ldg(&g_h2[((size_t)(b * S2 + s0 + r)) * F4 + f4]);
    } else if (slot == 3) {
#pragma unroll
        for (int r = 0; r < RT; ++r)
            if (s0 + r < S3) v[r] = __ldg(&g_h3[((size_t)(b * S3 + s0 + r)) * F4 + f4]);
    } else if (slot == 4) {
#pragma unroll
        for (int r = 0; r < RT; ++r) {
            const int s = s0 + r;
            if (s < S1) v[r] = __ldg(&g_h1[((size_t)(b * S1 + s)) * F4 + f4]);
            if (s < S2) add4(v[r], __ldg(&g_h2[((size_t)(b * S2 + s)) * F4 + f4]));
            if (s < S3) add4(v[r], __ldg(&g_h3[((size_t)(b * S3 + s)) * F4 + f4]));
        }
    } else {  // slot 0 or 5: lo3
#pragma unroll
        for (int r = 0; r < RT; ++r)
            if (s0 + r < S3) v[r] = __ldg(&g_l3[((size_t)(b * S3 + s0 + r)) * F4 + f4]);
    }

    const size_t o = (size_t)slot * SLOTSZ + ((size_t)(b * S0 + s0)) * F4 + f4;
#pragma unroll
    for (int r = 0; r < RT; ++r)
        __stcs(out + o + (size_t)r * F4, v[r]);
}

extern "C" void kernel_launch(void* const* d_in, const int* in_sizes, int n_in,
                              void* d_out, int out_size) {
    const float4* x = (const float4*)d_in[0];
    float4* out     = (float4*)d_out;

    coeff_k<<<dim3(NBLK3 + NBLK2 + NBLK1, NB), dim3(32, 4)>>>(x);
    assemble2_k<<<6144, 256>>>(out);
}